// round 1
// baseline (speedup 1.0000x reference)
#include <cuda_runtime.h>
#include <cstdint>

#define BATCH 16
#define NPTS  4096
#define DFEAT 64
#define SCTR  1024
#define KNB   32
#define C0    67      // 3 + 64 input channels
#define H0    64
#define H1    64
#define H2    128

// ---------------- device scratch (no allocations allowed) ----------------
__device__ int   g_ball_idx[BATCH * SCTR * KNB];
__device__ float g_W0[C0 * H0];   // [c][o]
__device__ float g_W1[H0 * H1];   // [c][o]
__device__ float g_W2[H1 * H2];   // [c][o]
__device__ float g_B0[H0];
__device__ float g_B1[H1];
__device__ float g_B2[H2];

// ---------------- weight folding: BN folded into W, b --------------------
__global__ void fold_kernel(
    const float* w0, const float* b0, const float* g0, const float* bt0, const float* m0, const float* v0,
    const float* w1, const float* b1, const float* g1, const float* bt1, const float* m1, const float* v1,
    const float* w2, const float* b2, const float* g2, const float* bt2, const float* m2, const float* v2)
{
    int t = threadIdx.x;
    const float eps = 1e-5f;
    // layer 0: w0 [64,67]
    for (int o = t; o < H0; o += blockDim.x) {
        float s = g0[o] * __frsqrt_rn(v0[o] + eps);
        g_B0[o] = (b0[o] - m0[o]) * s + bt0[o];
    }
    for (int i = t; i < H0 * C0; i += blockDim.x) {
        int o = i / C0, c = i % C0;
        float s = g0[o] * __frsqrt_rn(v0[o] + eps);
        g_W0[c * H0 + o] = w0[i] * s;
    }
    // layer 1: w1 [64,64]
    for (int o = t; o < H1; o += blockDim.x) {
        float s = g1[o] * __frsqrt_rn(v1[o] + eps);
        g_B1[o] = (b1[o] - m1[o]) * s + bt1[o];
    }
    for (int i = t; i < H1 * H0; i += blockDim.x) {
        int o = i / H0, c = i % H0;
        float s = g1[o] * __frsqrt_rn(v1[o] + eps);
        g_W1[c * H1 + o] = w1[i] * s;
    }
    // layer 2: w2 [128,64]
    for (int o = t; o < H2; o += blockDim.x) {
        float s = g2[o] * __frsqrt_rn(v2[o] + eps);
        g_B2[o] = (b2[o] - m2[o]) * s + bt2[o];
    }
    for (int i = t; i < H2 * H1; i += blockDim.x) {
        int o = i / H1, c = i % H1;
        float s = g2[o] * __frsqrt_rn(v2[o] + eps);
        g_W2[c * H2 + o] = w2[i] * s;
    }
}

// ---------------- FPS: one block per batch, 1024 threads -----------------
// distance form matches jnp.sum((xyz - centroid)**2, -1) with NO fma
// contraction: ((dx*dx) + (dy*dy)) + (dz*dz), all explicitly rounded.
__global__ __launch_bounds__(1024) void fps_kernel(
    const float* __restrict__ xyz, float* __restrict__ out_xyz, float* __restrict__ out_idx)
{
    extern __shared__ float smem[];
    float* sx = smem;            // [4096]
    float* sy = smem + NPTS;     // [4096]
    float* sz = smem + 2 * NPTS; // [4096]
    __shared__ unsigned swd[32];
    __shared__ int      swi[32];

    int b = blockIdx.x;
    const float* xb = xyz + (size_t)b * NPTS * 3;
    int tid = threadIdx.x, lane = tid & 31;

    float px[4], py[4], pz[4], dist[4];
#pragma unroll
    for (int j = 0; j < 4; j++) {
        int p = tid * 4 + j;
        float x = xb[3 * p], y = xb[3 * p + 1], z = xb[3 * p + 2];
        px[j] = x; py[j] = y; pz[j] = z;
        sx[p] = x; sy[p] = y; sz[p] = z;
        dist[j] = 1e10f;
    }
    __syncthreads();

    int far = 0;
    float* oxb = out_xyz + (size_t)b * SCTR * 3;
    float* oib = out_idx + (size_t)b * SCTR;

    for (int it = 0; it < SCTR; it++) {
        if (tid == 0) {
            oib[it] = (float)far;
            oxb[3 * it]     = sx[far];
            oxb[3 * it + 1] = sy[far];
            oxb[3 * it + 2] = sz[far];
        }
        if (it == SCTR - 1) break;

        float cx = sx[far], cy = sy[far], cz = sz[far];
        float best = -1.0f; int bidx = 0;
#pragma unroll
        for (int j = 0; j < 4; j++) {
            float dx = __fsub_rn(px[j], cx);
            float dy = __fsub_rn(py[j], cy);
            float dz = __fsub_rn(pz[j], cz);
            float d  = __fadd_rn(__fadd_rn(__fmul_rn(dx, dx), __fmul_rn(dy, dy)), __fmul_rn(dz, dz));
            d = fminf(dist[j], d);
            dist[j] = d;
            if (d > best) { best = d; bidx = tid * 4 + j; }
        }
        // warp argmax (positive floats monotonic as u32; lowest index on tie)
        unsigned ub = __float_as_uint(best);
        unsigned wm = __reduce_max_sync(0xffffffffu, ub);
        unsigned mk = __ballot_sync(0xffffffffu, ub == wm);
        int sl = __ffs(mk) - 1;
        int wi = __shfl_sync(0xffffffffu, bidx, sl);
        if (lane == 0) { swd[tid >> 5] = wm; swi[tid >> 5] = wi; }
        __syncthreads();
        // every warp reduces the 32 warp results (no second barrier needed)
        unsigned v = swd[lane];
        int ix = swi[lane];
        unsigned gm = __reduce_max_sync(0xffffffffu, v);
        unsigned m2 = __ballot_sync(0xffffffffu, v == gm);
        int sl2 = __ffs(m2) - 1;
        far = __shfl_sync(0xffffffffu, ix, sl2);
        __syncthreads();  // protect swd/swi for next iteration
    }
}

// ---------------- ball query: one warp per centroid ----------------------
// d = ((-2*dot) + |c|^2) + |p|^2, dot as fma chain (GEMM-like), matching
// the reference's square_distance formulation.
__global__ __launch_bounds__(256) void ball_kernel(
    const float* __restrict__ xyz, const float* __restrict__ new_xyz)
{
    extern __shared__ float smem[];
    float* sx  = smem;
    float* sy  = smem + NPTS;
    float* sz  = smem + 2 * NPTS;
    float* sn2 = smem + 3 * NPTS;

    int b = blockIdx.x >> 7;          // 128 blocks per batch
    int schunk = blockIdx.x & 127;
    const float* xb = xyz + (size_t)b * NPTS * 3;
    int tid = threadIdx.x;

    for (int p = tid; p < NPTS; p += 256) {
        float x = xb[3 * p], y = xb[3 * p + 1], z = xb[3 * p + 2];
        sx[p] = x; sy[p] = y; sz[p] = z;
        sn2[p] = __fadd_rn(__fadd_rn(__fmul_rn(x, x), __fmul_rn(y, y)), __fmul_rn(z, z));
    }
    __syncthreads();

    int warp = tid >> 5, lane = tid & 31;
    int s = schunk * 8 + warp;
    const float* c = new_xyz + ((size_t)b * SCTR + s) * 3;
    float cx = c[0], cy = c[1], cz = c[2];
    float cn2 = __fadd_rn(__fadd_rn(__fmul_rn(cx, cx), __fmul_rn(cy, cy)), __fmul_rn(cz, cz));
    const float R2 = (float)(0.4 * 0.4);

    int* out = g_ball_idx + ((size_t)b * SCTR + s) * KNB;
    int cnt = 0;
    float dmin = 3.402823466e38f; int imin = 0;

    for (int ch = 0; ch < NPTS / 32; ch++) {
        int p = ch * 32 + lane;
        float dot = __fmaf_rn(sz[p], cz, __fmaf_rn(sy[p], cy, __fmul_rn(sx[p], cx)));
        float d = __fadd_rn(__fadd_rn(__fmul_rn(-2.0f, dot), cn2), sn2[p]);
        if (d < dmin) { dmin = d; imin = p; }
        bool in = (d <= R2);
        unsigned mask = __ballot_sync(0xffffffffu, in);
        if (in) {
            int pos = cnt + __popc(mask & ((1u << lane) - 1u));
            if (pos < KNB) out[pos] = p;
        }
        cnt += __popc(mask);
        if (cnt >= KNB) break;
    }
    if (cnt < KNB) {
        // warp argmin with first-index tie-break
#pragma unroll
        for (int off = 16; off; off >>= 1) {
            float od = __shfl_down_sync(0xffffffffu, dmin, off);
            int   oi = __shfl_down_sync(0xffffffffu, imin, off);
            if (od < dmin || (od == dmin && oi < imin)) { dmin = od; imin = oi; }
        }
        imin = __shfl_sync(0xffffffffu, imin, 0);
        for (int q = cnt + lane; q < KNB; q += 32) out[q] = imin;
    }
}

// ---------------- fused gather + 3-layer MLP + max -----------------------
// block = 256 threads handles 32 centroids of one batch serially; weights
// cached in SMEM once per block. Activations channel-major [ch][36] pad.
#define SW0_OFF 0
#define SW1_OFF (C0 * H0)                        // 4288
#define SW2_OFF (SW1_OFF + H0 * H1)              // 8384
#define SB0_OFF (SW2_OFF + H1 * H2)              // 16576
#define SB1_OFF (SB0_OFF + H0)                   // 16640
#define SB2_OFF (SB1_OFF + H1)                   // 16704
#define SX_OFF  (SB2_OFF + H2)                   // 16832
#define SA0_OFF (SX_OFF + C0 * 36)               // 19244
#define SA1_OFF (SA0_OFF + H0 * 36)              // 21548
#define SA2_OFF (SA1_OFF + H1 * 36)              // 23852
#define SIDX_OFF (SA2_OFF + H2 * 36)             // 28460
#define MLP_SMEM_FLOATS (SIDX_OFF + KNB)         // 28492
#define MLP_SMEM_BYTES  (MLP_SMEM_FLOATS * 4)

__global__ __launch_bounds__(256) void mlp_kernel(
    const float* __restrict__ xyz, const float* __restrict__ feat,
    const float* __restrict__ new_xyz, float* __restrict__ out_feat)
{
    extern __shared__ float smem[];
    float* sW0 = smem + SW0_OFF;
    float* sW1 = smem + SW1_OFF;
    float* sW2 = smem + SW2_OFF;
    float* sB0 = smem + SB0_OFF;
    float* sB1 = smem + SB1_OFF;
    float* sB2 = smem + SB2_OFF;
    float* sX  = smem + SX_OFF;
    float* sA0 = smem + SA0_OFF;
    float* sA1 = smem + SA1_OFF;
    float* sA2 = smem + SA2_OFF;
    int*   sIdx = (int*)(smem + SIDX_OFF);

    int tid = threadIdx.x;
    for (int i = tid; i < C0 * H0; i += 256) sW0[i] = g_W0[i];
    for (int i = tid; i < H0 * H1; i += 256) sW1[i] = g_W1[i];
    for (int i = tid; i < H1 * H2; i += 256) sW2[i] = g_W2[i];
    if (tid < H0) sB0[tid] = g_B0[tid];
    if (tid < H1) sB1[tid] = g_B1[tid];
    if (tid < H2) sB2[tid] = g_B2[tid];

    int b  = blockIdx.x >> 5;            // 32 blocks per batch
    int s0 = (blockIdx.x & 31) * 32;
    const float* xb = xyz + (size_t)b * NPTS * 3;
    const float* fb = feat + (size_t)b * NPTS * DFEAT;
    __syncthreads();

    for (int si = 0; si < 32; si++) {
        int s = s0 + si;
        if (tid < KNB) sIdx[tid] = g_ball_idx[((size_t)b * SCTR + s) * KNB + tid];
        __syncthreads();

        // ---- gather: xyz (relative) + features, channel-major ----
        const float* c = new_xyz + ((size_t)b * SCTR + s) * 3;
        if (tid < KNB) {
            int p = sIdx[tid];
            sX[0 * 36 + tid] = xb[3 * p]     - c[0];
            sX[1 * 36 + tid] = xb[3 * p + 1] - c[1];
            sX[2 * 36 + tid] = xb[3 * p + 2] - c[2];
        }
        {
            int k = tid >> 3;
            int f0 = (tid & 7) * 8;
            int p = sIdx[k];
            const float4* fp = (const float4*)(fb + (size_t)p * DFEAT + f0);
            float4 va = fp[0], vb = fp[1];
            sX[(3 + f0 + 0) * 36 + k] = va.x;
            sX[(3 + f0 + 1) * 36 + k] = va.y;
            sX[(3 + f0 + 2) * 36 + k] = va.z;
            sX[(3 + f0 + 3) * 36 + k] = va.w;
            sX[(3 + f0 + 4) * 36 + k] = vb.x;
            sX[(3 + f0 + 5) * 36 + k] = vb.y;
            sX[(3 + f0 + 6) * 36 + k] = vb.z;
            sX[(3 + f0 + 7) * 36 + k] = vb.w;
        }
        __syncthreads();

        // ---- layer 0: 67 -> 64, thread tile 4o x 2k ----
        {
            int ob = (tid & 15) * 4;
            int kb = (tid >> 4) * 2;
            float acc[4][2] = {};
            for (int cc = 0; cc < C0; cc++) {
                float2 a = *(const float2*)(sX + cc * 36 + kb);
                float4 w = *(const float4*)(sW0 + cc * H0 + ob);
                acc[0][0] += w.x * a.x; acc[0][1] += w.x * a.y;
                acc[1][0] += w.y * a.x; acc[1][1] += w.y * a.y;
                acc[2][0] += w.z * a.x; acc[2][1] += w.z * a.y;
                acc[3][0] += w.w * a.x; acc[3][1] += w.w * a.y;
            }
#pragma unroll
            for (int o = 0; o < 4; o++) {
                float bb = sB0[ob + o];
                sA0[(ob + o) * 36 + kb]     = fmaxf(acc[o][0] + bb, 0.0f);
                sA0[(ob + o) * 36 + kb + 1] = fmaxf(acc[o][1] + bb, 0.0f);
            }
        }
        __syncthreads();

        // ---- layer 1: 64 -> 64, thread tile 4o x 2k ----
        {
            int ob = (tid & 15) * 4;
            int kb = (tid >> 4) * 2;
            float acc[4][2] = {};
            for (int cc = 0; cc < H0; cc++) {
                float2 a = *(const float2*)(sA0 + cc * 36 + kb);
                float4 w = *(const float4*)(sW1 + cc * H1 + ob);
                acc[0][0] += w.x * a.x; acc[0][1] += w.x * a.y;
                acc[1][0] += w.y * a.x; acc[1][1] += w.y * a.y;
                acc[2][0] += w.z * a.x; acc[2][1] += w.z * a.y;
                acc[3][0] += w.w * a.x; acc[3][1] += w.w * a.y;
            }
#pragma unroll
            for (int o = 0; o < 4; o++) {
                float bb = sB1[ob + o];
                sA1[(ob + o) * 36 + kb]     = fmaxf(acc[o][0] + bb, 0.0f);
                sA1[(ob + o) * 36 + kb + 1] = fmaxf(acc[o][1] + bb, 0.0f);
            }
        }
        __syncthreads();

        // ---- layer 2: 64 -> 128, thread tile 4o x 4k ----
        {
            int ob = (tid & 31) * 4;
            int kb = (tid >> 5) * 4;
            float acc[4][4] = {};
            for (int cc = 0; cc < H1; cc++) {
                float4 a = *(const float4*)(sA1 + cc * 36 + kb);
                float4 w = *(const float4*)(sW2 + cc * H2 + ob);
                acc[0][0] += w.x * a.x; acc[0][1] += w.x * a.y; acc[0][2] += w.x * a.z; acc[0][3] += w.x * a.w;
                acc[1][0] += w.y * a.x; acc[1][1] += w.y * a.y; acc[1][2] += w.y * a.z; acc[1][3] += w.y * a.w;
                acc[2][0] += w.z * a.x; acc[2][1] += w.z * a.y; acc[2][2] += w.z * a.z; acc[2][3] += w.z * a.w;
                acc[3][0] += w.w * a.x; acc[3][1] += w.w * a.y; acc[3][2] += w.w * a.z; acc[3][3] += w.w * a.w;
            }
#pragma unroll
            for (int o = 0; o < 4; o++) {
                float bb = sB2[ob + o];
#pragma unroll
                for (int k = 0; k < 4; k++)
                    sA2[(ob + o) * 36 + kb + k] = fmaxf(acc[o][k] + bb, 0.0f);
            }
        }
        __syncthreads();

        // ---- max over K neighbors ----
        if (tid < H2) {
            const float* row = sA2 + tid * 36;
            float m = row[0];
#pragma unroll
            for (int k = 1; k < KNB; k++) m = fmaxf(m, row[k]);
            out_feat[((size_t)b * SCTR + s) * H2 + tid] = m;
        }
        __syncthreads();
    }
}

// ---------------------------- launcher -----------------------------------
extern "C" void kernel_launch(void* const* d_in, const int* in_sizes, int n_in,
                              void* d_out, int out_size)
{
    const float* xyz  = (const float*)d_in[0];
    const float* feat = (const float*)d_in[1];

    float* out = (float*)d_out;
    float* out_xyz  = out;                       // [16,1024,3]
    float* out_feat = out + BATCH * SCTR * 3;    // [16,1024,128]
    float* out_idx  = out + BATCH * SCTR * 3 + BATCH * SCTR * H2;  // [16,1024]

    const size_t fps_smem  = (size_t)3 * NPTS * 4;   // 48 KB
    const size_t ball_smem = (size_t)4 * NPTS * 4;   // 64 KB
    cudaFuncSetAttribute(fps_kernel,  cudaFuncAttributeMaxDynamicSharedMemorySize, (int)fps_smem);
    cudaFuncSetAttribute(ball_kernel, cudaFuncAttributeMaxDynamicSharedMemorySize, (int)ball_smem);
    cudaFuncSetAttribute(mlp_kernel,  cudaFuncAttributeMaxDynamicSharedMemorySize, MLP_SMEM_BYTES);

    fold_kernel<<<1, 256>>>(
        (const float*)d_in[2],  (const float*)d_in[3],  (const float*)d_in[4],
        (const float*)d_in[5],  (const float*)d_in[6],  (const float*)d_in[7],
        (const float*)d_in[8],  (const float*)d_in[9],  (const float*)d_in[10],
        (const float*)d_in[11], (const float*)d_in[12], (const float*)d_in[13],
        (const float*)d_in[14], (const float*)d_in[15], (const float*)d_in[16],
        (const float*)d_in[17], (const float*)d_in[18], (const float*)d_in[19]);

    fps_kernel<<<BATCH, 1024, fps_smem>>>(xyz, out_xyz, out_idx);
    ball_kernel<<<BATCH * (SCTR / 8), 256, ball_smem>>>(xyz, out_xyz);
    mlp_kernel<<<BATCH * (SCTR / 32), 256, MLP_SMEM_BYTES>>>(xyz, feat, out_xyz, out_feat);
}

// round 2
// speedup vs baseline: 1.5022x; 1.5022x over previous
#include <cuda_runtime.h>
#include <cstdint>

#define BATCH 16
#define NPTS  4096
#define DFEAT 64
#define SCTR  1024
#define KNB   32
#define C0    67      // 3 + 64 input channels
#define H0    64
#define H1    64
#define H2    128

typedef unsigned long long ull;

// ---------------- f32x2 packed helpers (sm_100a) --------------------------
__device__ __forceinline__ ull pack2(float x) {
    unsigned xi = __float_as_uint(x);
    ull r; asm("mov.b64 %0, {%1, %1};" : "=l"(r) : "r"(xi)); return r;
}
__device__ __forceinline__ ull packab(float a, float b) {
    unsigned ai = __float_as_uint(a), bi = __float_as_uint(b);
    ull r; asm("mov.b64 %0, {%1, %2};" : "=l"(r) : "r"(ai), "r"(bi)); return r;
}
__device__ __forceinline__ float2 unpk(ull v) {
    unsigned lo, hi; asm("mov.b64 {%0, %1}, %2;" : "=r"(lo), "=r"(hi) : "l"(v));
    return make_float2(__uint_as_float(lo), __uint_as_float(hi));
}
__device__ __forceinline__ ull add2(ull a, ull b) {
    ull r; asm("add.rn.f32x2 %0, %1, %2;" : "=l"(r) : "l"(a), "l"(b)); return r;
}
__device__ __forceinline__ ull mul2(ull a, ull b) {
    ull r; asm("mul.rn.f32x2 %0, %1, %2;" : "=l"(r) : "l"(a), "l"(b)); return r;
}
__device__ __forceinline__ void fma2(ull &d, ull a, ull b) {
    asm("fma.rn.f32x2 %0, %1, %2, %0;" : "+l"(d) : "l"(a), "l"(b));
}

// ---------------- device scratch (no allocations allowed) ----------------
__device__ int   g_ball_idx[BATCH * SCTR * KNB];
__device__ float g_W0[C0 * H0];   // [c][o]
__device__ float g_W1[H0 * H1];   // [c][o]
__device__ float g_W2[H1 * H2];   // [c][o]
__device__ float g_B0[H0];
__device__ float g_B1[H1];
__device__ float g_B2[H2];

// ---------------- weight folding: BN folded into W, b --------------------
__global__ void fold_kernel(
    const float* w0, const float* b0, const float* g0, const float* bt0, const float* m0, const float* v0,
    const float* w1, const float* b1, const float* g1, const float* bt1, const float* m1, const float* v1,
    const float* w2, const float* b2, const float* g2, const float* bt2, const float* m2, const float* v2)
{
    int t = threadIdx.x;
    const float eps = 1e-5f;
    for (int o = t; o < H0; o += blockDim.x) {
        float s = g0[o] * __frsqrt_rn(v0[o] + eps);
        g_B0[o] = (b0[o] - m0[o]) * s + bt0[o];
    }
    for (int i = t; i < H0 * C0; i += blockDim.x) {
        int o = i / C0, c = i % C0;
        float s = g0[o] * __frsqrt_rn(v0[o] + eps);
        g_W0[c * H0 + o] = w0[i] * s;
    }
    for (int o = t; o < H1; o += blockDim.x) {
        float s = g1[o] * __frsqrt_rn(v1[o] + eps);
        g_B1[o] = (b1[o] - m1[o]) * s + bt1[o];
    }
    for (int i = t; i < H1 * H0; i += blockDim.x) {
        int o = i / H0, c = i % H0;
        float s = g1[o] * __frsqrt_rn(v1[o] + eps);
        g_W1[c * H1 + o] = w1[i] * s;
    }
    for (int o = t; o < H2; o += blockDim.x) {
        float s = g2[o] * __frsqrt_rn(v2[o] + eps);
        g_B2[o] = (b2[o] - m2[o]) * s + bt2[o];
    }
    for (int i = t; i < H2 * H1; i += blockDim.x) {
        int o = i / H1, c = i % H1;
        float s = g2[o] * __frsqrt_rn(v2[o] + eps);
        g_W2[c * H2 + o] = w2[i] * s;
    }
}

// ---------------- FPS: one block per batch, 1024 threads ------------------
// f32x2 packed distance update; per-lane IEEE rn => bit-identical to the
// scalar ((dx*dx)+(dy*dy))+(dz*dz) form that passed round 1.
__global__ __launch_bounds__(1024) void fps_kernel(
    const float* __restrict__ xyz, float* __restrict__ out_xyz, float* __restrict__ out_idx)
{
    extern __shared__ float smem[];
    float* sx = smem;            // [4096]
    float* sy = smem + NPTS;
    float* sz = smem + 2 * NPTS;
    __shared__ unsigned swd[2][32];
    __shared__ int      swi[2][32];

    int b = blockIdx.x;
    const float* xb = xyz + (size_t)b * NPTS * 3;
    int tid = threadIdx.x, lane = tid & 31, wid = tid >> 5;

    float xs[4], ys[4], zs[4];
#pragma unroll
    for (int j = 0; j < 4; j++) {
        int p = tid * 4 + j;
        xs[j] = xb[3 * p]; ys[j] = xb[3 * p + 1]; zs[j] = xb[3 * p + 2];
        sx[p] = xs[j]; sy[p] = ys[j]; sz[p] = zs[j];
    }
    ull px2[2], py2[2], pz2[2];
    px2[0] = packab(xs[0], xs[1]); px2[1] = packab(xs[2], xs[3]);
    py2[0] = packab(ys[0], ys[1]); py2[1] = packab(ys[2], ys[3]);
    pz2[0] = packab(zs[0], zs[1]); pz2[1] = packab(zs[2], zs[3]);
    float d0 = 1e10f, d1 = 1e10f, d2 = 1e10f, d3 = 1e10f;
    __syncthreads();

    int far = 0;
    float* oxb = out_xyz + (size_t)b * SCTR * 3;
    float* oib = out_idx + (size_t)b * SCTR;

    for (int it = 0; it < SCTR; it++) {
        if (tid == 0) {
            oib[it] = (float)far;
            oxb[3 * it]     = sx[far];
            oxb[3 * it + 1] = sy[far];
            oxb[3 * it + 2] = sz[far];
        }
        if (it == SCTR - 1) break;

        float cx = sx[far], cy = sy[far], cz = sz[far];
        ull cxn = pack2(-cx), cyn = pack2(-cy), czn = pack2(-cz);

        ull dxa = add2(px2[0], cxn), dya = add2(py2[0], cyn), dza = add2(pz2[0], czn);
        ull qa = add2(add2(mul2(dxa, dxa), mul2(dya, dya)), mul2(dza, dza));
        ull dxb = add2(px2[1], cxn), dyb = add2(py2[1], cyn), dzb = add2(pz2[1], czn);
        ull qb = add2(add2(mul2(dxb, dxb), mul2(dyb, dyb)), mul2(dzb, dzb));
        float2 fa = unpk(qa), fb2 = unpk(qb);
        d0 = fminf(d0, fa.x); d1 = fminf(d1, fa.y);
        d2 = fminf(d2, fb2.x); d3 = fminf(d3, fb2.y);

        float best = fmaxf(fmaxf(d0, d1), fmaxf(d2, d3));
        int j = (d0 == best) ? 0 : (d1 == best) ? 1 : (d2 == best) ? 2 : 3;
        int bidx = tid * 4 + j;

        unsigned ub = __float_as_uint(best);
        unsigned wm = __reduce_max_sync(0xffffffffu, ub);
        unsigned mk = __ballot_sync(0xffffffffu, ub == wm);
        int sl = __ffs(mk) - 1;
        int wi = __shfl_sync(0xffffffffu, bidx, sl);
        int buf = it & 1;
        if (lane == 0) { swd[buf][wid] = wm; swi[buf][wid] = wi; }
        __syncthreads();
        unsigned v = swd[buf][lane];
        int ix = swi[buf][lane];
        unsigned gm = __reduce_max_sync(0xffffffffu, v);
        unsigned m2 = __ballot_sync(0xffffffffu, v == gm);
        far = __shfl_sync(0xffffffffu, ix, __ffs(m2) - 1);
        // no second barrier: next iteration writes the other buffer, and no
        // warp can get 2 iterations ahead (it would block at the next bar).
    }
}

// ---------------- ball query: one warp per centroid (unchanged math) ------
__global__ __launch_bounds__(256) void ball_kernel(
    const float* __restrict__ xyz, const float* __restrict__ new_xyz)
{
    extern __shared__ float smem[];
    float* sx  = smem;
    float* sy  = smem + NPTS;
    float* sz  = smem + 2 * NPTS;
    float* sn2 = smem + 3 * NPTS;

    int b = blockIdx.x >> 7;
    int schunk = blockIdx.x & 127;
    const float* xb = xyz + (size_t)b * NPTS * 3;
    int tid = threadIdx.x;

    for (int p = tid; p < NPTS; p += 256) {
        float x = xb[3 * p], y = xb[3 * p + 1], z = xb[3 * p + 2];
        sx[p] = x; sy[p] = y; sz[p] = z;
        sn2[p] = __fadd_rn(__fadd_rn(__fmul_rn(x, x), __fmul_rn(y, y)), __fmul_rn(z, z));
    }
    __syncthreads();

    int warp = tid >> 5, lane = tid & 31;
    int s = schunk * 8 + warp;
    const float* c = new_xyz + ((size_t)b * SCTR + s) * 3;
    float cx = c[0], cy = c[1], cz = c[2];
    float cn2 = __fadd_rn(__fadd_rn(__fmul_rn(cx, cx), __fmul_rn(cy, cy)), __fmul_rn(cz, cz));
    const float R2 = (float)(0.4 * 0.4);

    int* out = g_ball_idx + ((size_t)b * SCTR + s) * KNB;
    int cnt = 0;
    float dmin = 3.402823466e38f; int imin = 0;

    for (int ch = 0; ch < NPTS / 32; ch++) {
        int p = ch * 32 + lane;
        float dot = __fmaf_rn(sz[p], cz, __fmaf_rn(sy[p], cy, __fmul_rn(sx[p], cx)));
        float d = __fadd_rn(__fadd_rn(__fmul_rn(-2.0f, dot), cn2), sn2[p]);
        if (d < dmin) { dmin = d; imin = p; }
        bool in = (d <= R2);
        unsigned mask = __ballot_sync(0xffffffffu, in);
        if (in) {
            int pos = cnt + __popc(mask & ((1u << lane) - 1u));
            if (pos < KNB) out[pos] = p;
        }
        cnt += __popc(mask);
        if (cnt >= KNB) break;
    }
    if (cnt < KNB) {
#pragma unroll
        for (int off = 16; off; off >>= 1) {
            float od = __shfl_down_sync(0xffffffffu, dmin, off);
            int   oi = __shfl_down_sync(0xffffffffu, imin, off);
            if (od < dmin || (od == dmin && oi < imin)) { dmin = od; imin = oi; }
        }
        imin = __shfl_sync(0xffffffffu, imin, 0);
        for (int q = cnt + lane; q < KNB; q += 32) out[q] = imin;
    }
}

// ---------------- fused gather + 3-layer MLP + max (f32x2) ----------------
// 512 threads; 8 centroids per group (K-columns = 256); 2 groups per block.
#define KS   264                 // padded column stride
#define KC   256                 // k columns per group (8 centroids x 32)
#define SW0_OFF 0
#define SW1_OFF (C0 * H0)                         // 4288
#define SW2_OFF (SW1_OFF + H0 * H1)               // 8384
#define SB0_OFF (SW2_OFF + H1 * H2)               // 16576
#define SB1_OFF (SB0_OFF + H0)
#define SB2_OFF (SB1_OFF + H1)
#define SX_OFF  (SB2_OFF + H2)                    // 16832
#define SA0_OFF (SX_OFF + C0 * KS)                // 16832 + 17688 = 34520
#define MLP_SMEM_FLOATS (SA0_OFF + H0 * KS)       // 34520 + 16896 = 51416
#define MLP_SMEM_BYTES  (MLP_SMEM_FLOATS * 4)     // 205,664 B

// one MLP layer: out[o][k] = relu(sum_c W[c][o]*src[c][k] + B[o])
// pack over output-channel pairs -> weights load as natural f32x2 pairs.
template<int CIN>
__device__ __forceinline__ void mlp_layer(
    const float* __restrict__ src, float* __restrict__ dst,
    const float* __restrict__ W, const float* __restrict__ Bs, int tid)
{
    int o0 = (tid >> 6) * 8;     // 8 o-tiles of 8
    int k0 = (tid & 63) * 4;     // 64 k-tiles of 4
    ull acc[4][4];
#pragma unroll
    for (int a = 0; a < 4; a++)
#pragma unroll
        for (int kk = 0; kk < 4; kk++) acc[a][kk] = 0ull;

    const float* xr = src + k0;
    const float* wr = W + o0;
    for (int c = 0; c < CIN; c++) {
        ulonglong2 wa = *(const ulonglong2*)(wr);      // o0..o0+3 (2 f32x2)
        ulonglong2 wb = *(const ulonglong2*)(wr + 4);  // o0+4..o0+7
        float4 xv = *(const float4*)(xr);
        ull x0 = pack2(xv.x), x1 = pack2(xv.y), x2 = pack2(xv.z), x3 = pack2(xv.w);
        fma2(acc[0][0], wa.x, x0); fma2(acc[0][1], wa.x, x1); fma2(acc[0][2], wa.x, x2); fma2(acc[0][3], wa.x, x3);
        fma2(acc[1][0], wa.y, x0); fma2(acc[1][1], wa.y, x1); fma2(acc[1][2], wa.y, x2); fma2(acc[1][3], wa.y, x3);
        fma2(acc[2][0], wb.x, x0); fma2(acc[2][1], wb.x, x1); fma2(acc[2][2], wb.x, x2); fma2(acc[2][3], wb.x, x3);
        fma2(acc[3][0], wb.y, x0); fma2(acc[3][1], wb.y, x1); fma2(acc[3][2], wb.y, x2); fma2(acc[3][3], wb.y, x3);
        xr += KS; wr += 64;
    }
#pragma unroll
    for (int o2 = 0; o2 < 4; o2++) {
        float2 bb = *(const float2*)(Bs + o0 + 2 * o2);
        float* dA = dst + (o0 + 2 * o2) * KS + k0;
        float* dB = dA + KS;
#pragma unroll
        for (int kk = 0; kk < 4; kk++) {
            float2 v = unpk(acc[o2][kk]);
            dA[kk] = fmaxf(v.x + bb.x, 0.0f);
            dB[kk] = fmaxf(v.y + bb.y, 0.0f);
        }
    }
}

__global__ __launch_bounds__(512, 1) void mlp_kernel(
    const float* __restrict__ xyz, const float* __restrict__ feat,
    const float* __restrict__ new_xyz, float* __restrict__ out_feat)
{
    extern __shared__ float smem[];
    float* sW0 = smem + SW0_OFF;
    float* sW1 = smem + SW1_OFF;
    float* sW2 = smem + SW2_OFF;
    float* sB0 = smem + SB0_OFF;
    float* sB1 = smem + SB1_OFF;
    float* sB2 = smem + SB2_OFF;
    float* sX  = smem + SX_OFF;   // also holds A1 (64 rows fit in 67)
    float* sA0 = smem + SA0_OFF;

    int tid = threadIdx.x;
    for (int i = tid; i < C0 * H0; i += 512) sW0[i] = g_W0[i];
    for (int i = tid; i < H0 * H1; i += 512) sW1[i] = g_W1[i];
    for (int i = tid; i < H1 * H2; i += 512) sW2[i] = g_W2[i];
    if (tid < H0) sB0[tid] = g_B0[tid];
    if (tid < H1) sB1[tid] = g_B1[tid];
    if (tid < H2) sB2[tid] = g_B2[tid];

    int gid = blockIdx.x;
    int b  = gid >> 6;                 // 64 blocks per batch
    int g0 = (gid & 63) * 2;           // 2 groups per block
    const float* xb = xyz + (size_t)b * NPTS * 3;
    const float* fb = feat + (size_t)b * NPTS * DFEAT;

    for (int gg = 0; gg < 2; gg++) {
        int s0 = (g0 + gg) * 8;        // 8 centroids this group
        __syncthreads();               // sX reusable / weights visible

        // ---- gather xyz-relative (rows 0..2), 256 threads = 256 cols ----
        if (tid < KC) {
            int col = tid;
            int cent = col >> 5;
            int p = g_ball_idx[((size_t)b * SCTR + s0 + cent) * KNB + (col & 31)];
            const float* cc = new_xyz + ((size_t)b * SCTR + s0 + cent) * 3;
            sX[0 * KS + col] = xb[3 * p]     - cc[0];
            sX[1 * KS + col] = xb[3 * p + 1] - cc[1];
            sX[2 * KS + col] = xb[3 * p + 2] - cc[2];
        }
        // ---- gather features (rows 3..66): 2 threads per column ----
        {
            int col = tid >> 1, half = tid & 1;
            int cent = col >> 5;
            int p = g_ball_idx[((size_t)b * SCTR + s0 + cent) * KNB + (col & 31)];
            const float4* fp = (const float4*)(fb + (size_t)p * DFEAT + half * 32);
#pragma unroll
            for (int f4 = 0; f4 < 8; f4++) {
                float4 v = fp[f4];
                int r = 3 + half * 32 + f4 * 4;
                sX[(r + 0) * KS + col] = v.x;
                sX[(r + 1) * KS + col] = v.y;
                sX[(r + 2) * KS + col] = v.z;
                sX[(r + 3) * KS + col] = v.w;
            }
        }
        __syncthreads();

        mlp_layer<C0>(sX, sA0, sW0, sB0, tid);   // 67 -> 64
        __syncthreads();
        mlp_layer<H0>(sA0, sX, sW1, sB1, tid);   // 64 -> 64 (A1 overlays X)
        __syncthreads();

        // ---- layer 2 (64 -> 128) fused with bias+relu+max over K ----
        {
            int o0 = (tid >> 5) * 8;   // 16 o-tiles of 8
            int k0 = (tid & 31) * 8;   // 32 k-tiles of 8
            ull acc[4][8];
#pragma unroll
            for (int a = 0; a < 4; a++)
#pragma unroll
                for (int kk = 0; kk < 8; kk++) acc[a][kk] = 0ull;

            const float* xr = sX + k0;
            const float* wr = sW2 + o0;
            for (int c = 0; c < H1; c++) {
                ulonglong2 wa = *(const ulonglong2*)(wr);
                ulonglong2 wb = *(const ulonglong2*)(wr + 4);
                float4 xv0 = *(const float4*)(xr);
                float4 xv1 = *(const float4*)(xr + 4);
                ull x0 = pack2(xv0.x), x1 = pack2(xv0.y), x2 = pack2(xv0.z), x3 = pack2(xv0.w);
                ull x4 = pack2(xv1.x), x5 = pack2(xv1.y), x6 = pack2(xv1.z), x7 = pack2(xv1.w);
                fma2(acc[0][0], wa.x, x0); fma2(acc[0][1], wa.x, x1); fma2(acc[0][2], wa.x, x2); fma2(acc[0][3], wa.x, x3);
                fma2(acc[0][4], wa.x, x4); fma2(acc[0][5], wa.x, x5); fma2(acc[0][6], wa.x, x6); fma2(acc[0][7], wa.x, x7);
                fma2(acc[1][0], wa.y, x0); fma2(acc[1][1], wa.y, x1); fma2(acc[1][2], wa.y, x2); fma2(acc[1][3], wa.y, x3);
                fma2(acc[1][4], wa.y, x4); fma2(acc[1][5], wa.y, x5); fma2(acc[1][6], wa.y, x6); fma2(acc[1][7], wa.y, x7);
                fma2(acc[2][0], wb.x, x0); fma2(acc[2][1], wb.x, x1); fma2(acc[2][2], wb.x, x2); fma2(acc[2][3], wb.x, x3);
                fma2(acc[2][4], wb.x, x4); fma2(acc[2][5], wb.x, x5); fma2(acc[2][6], wb.x, x6); fma2(acc[2][7], wb.x, x7);
                fma2(acc[3][0], wb.y, x0); fma2(acc[3][1], wb.y, x1); fma2(acc[3][2], wb.y, x2); fma2(acc[3][3], wb.y, x3);
                fma2(acc[3][4], wb.y, x4); fma2(acc[3][5], wb.y, x5); fma2(acc[3][6], wb.y, x6); fma2(acc[3][7], wb.y, x7);
                xr += KS; wr += H2;
            }

            int lane = tid & 31;
            float ov[8];
#pragma unroll
            for (int o2 = 0; o2 < 4; o2++) {
                float2 bb = *(const float2*)(sB2 + o0 + 2 * o2);
                float2 m = unpk(acc[o2][0]);
#pragma unroll
                for (int kk = 1; kk < 8; kk++) {
                    float2 v = unpk(acc[o2][kk]);
                    m.x = fmaxf(m.x, v.x);
                    m.y = fmaxf(m.y, v.y);
                }
                // 4 threads share one centroid (lane groups of 4)
                m.x = fmaxf(m.x, __shfl_xor_sync(0xffffffffu, m.x, 1));
                m.x = fmaxf(m.x, __shfl_xor_sync(0xffffffffu, m.x, 2));
                m.y = fmaxf(m.y, __shfl_xor_sync(0xffffffffu, m.y, 1));
                m.y = fmaxf(m.y, __shfl_xor_sync(0xffffffffu, m.y, 2));
                ov[2 * o2]     = fmaxf(m.x + bb.x, 0.0f);
                ov[2 * o2 + 1] = fmaxf(m.y + bb.y, 0.0f);
            }
            if ((lane & 3) == 0) {
                int cent = lane >> 2;
                float* dst = out_feat + ((size_t)b * SCTR + s0 + cent) * H2 + o0;
                *(float4*)(dst)     = make_float4(ov[0], ov[1], ov[2], ov[3]);
                *(float4*)(dst + 4) = make_float4(ov[4], ov[5], ov[6], ov[7]);
            }
        }
    }
}

// ---------------------------- launcher -----------------------------------
extern "C" void kernel_launch(void* const* d_in, const int* in_sizes, int n_in,
                              void* d_out, int out_size)
{
    const float* xyz  = (const float*)d_in[0];
    const float* feat = (const float*)d_in[1];

    float* out = (float*)d_out;
    float* out_xyz  = out;                       // [16,1024,3]
    float* out_feat = out + BATCH * SCTR * 3;    // [16,1024,128]
    float* out_idx  = out + BATCH * SCTR * 3 + BATCH * SCTR * H2;  // [16,1024]

    const size_t fps_smem  = (size_t)3 * NPTS * 4;   // 48 KB
    const size_t ball_smem = (size_t)4 * NPTS * 4;   // 64 KB
    cudaFuncSetAttribute(fps_kernel,  cudaFuncAttributeMaxDynamicSharedMemorySize, (int)fps_smem);
    cudaFuncSetAttribute(ball_kernel, cudaFuncAttributeMaxDynamicSharedMemorySize, (int)ball_smem);
    cudaFuncSetAttribute(mlp_kernel,  cudaFuncAttributeMaxDynamicSharedMemorySize, MLP_SMEM_BYTES);

    fold_kernel<<<1, 256>>>(
        (const float*)d_in[2],  (const float*)d_in[3],  (const float*)d_in[4],
        (const float*)d_in[5],  (const float*)d_in[6],  (const float*)d_in[7],
        (const float*)d_in[8],  (const float*)d_in[9],  (const float*)d_in[10],
        (const float*)d_in[11], (const float*)d_in[12], (const float*)d_in[13],
        (const float*)d_in[14], (const float*)d_in[15], (const float*)d_in[16],
        (const float*)d_in[17], (const float*)d_in[18], (const float*)d_in[19]);

    fps_kernel<<<BATCH, 1024, fps_smem>>>(xyz, out_xyz, out_idx);
    ball_kernel<<<BATCH * (SCTR / 8), 256, ball_smem>>>(xyz, out_xyz);
    mlp_kernel<<<BATCH * 64, 512, MLP_SMEM_BYTES>>>(xyz, feat, out_xyz, out_feat);
}